// round 6
// baseline (speedup 1.0000x reference)
#include <cuda_runtime.h>
#include <cuda_bf16.h>
#include <cuda_fp8.h>
#include <cstdint>
#include <math.h>

// ---------------- problem constants ----------------
#define NQ     4096
#define NM     100000
#define D      128
#define NCH    37
#define CHUNK  2703          // ceil(NM / NCH)
#define QT     128           // queries per CTA (block M)
#define NT     128           // memory rows per tile (block N)
#define KC     8             // candidates kept per (query, chunk)

#define A_BYTES   (QT * D)              // fp8: 16384
#define B_BYTES   (NT * D)              // 16384
#define NBUF      3
#define SMEM_DYN  (A_BYTES + NBUF * B_BYTES + 1024)   // ~66KB

// ---------------- device scratch ----------------
__device__ float     g_qn[NQ * D];        // normalized queries (fp32)
__device__ uint32_t  g_qf8[NQ * 32];      // normalized queries (e4m3, 4/word)
__device__ uint32_t  g_mf8[NM * 32];      // normalized memory (e4m3)
__device__ float     g_invm[NM];          // 1/||m||
__device__ float     g_cv[NQ * NCH * KC];
__device__ int       g_ci[NQ * NCH * KC];

// ---------------- PTX helpers (family-generic, sm_89-era max) ----------------
__device__ __forceinline__ uint32_t s2u(const void* p) {
    uint32_t a;
    asm("{ .reg .u64 t; cvta.to.shared.u64 t, %1; cvt.u32.u64 %0, t; }"
        : "=r"(a) : "l"(p));
    return a;
}

__device__ __forceinline__ void cp16(uint32_t dst, const void* src) {
    asm volatile("cp.async.cg.shared.global [%0], [%1], 16;" :: "r"(dst), "l"(src));
}
#define CP_COMMIT() asm volatile("cp.async.commit_group;" ::: "memory")
#define CP_WAIT0()  asm volatile("cp.async.wait_group 0;" ::: "memory")
#define CP_WAIT1()  asm volatile("cp.async.wait_group 1;" ::: "memory")

__device__ __forceinline__ void ldsm_x4(uint32_t addr, uint32_t& r0, uint32_t& r1,
                                        uint32_t& r2, uint32_t& r3) {
    asm volatile("ldmatrix.sync.aligned.m8n8.x4.shared.b16 {%0,%1,%2,%3}, [%4];"
        : "=r"(r0), "=r"(r1), "=r"(r2), "=r"(r3) : "r"(addr));
}

// fp8 e4m3 MMA: m16n8k32
__device__ __forceinline__ void mma16832(float* d, const uint32_t* a, const uint32_t* b) {
    asm volatile("mma.sync.aligned.m16n8k32.row.col.f32.e4m3.e4m3.f32 "
        "{%0,%1,%2,%3}, {%4,%5,%6,%7}, {%8,%9}, {%0,%1,%2,%3};"
        : "+f"(d[0]), "+f"(d[1]), "+f"(d[2]), "+f"(d[3])
        : "r"(a[0]), "r"(a[1]), "r"(a[2]), "r"(a[3]), "r"(b[0]), "r"(b[1]));
}

// swizzled byte offset: rows of 128 bytes, 16B chunks XOR-permuted per row
__device__ __forceinline__ uint32_t sw_off(int row, int c16) {
    return (uint32_t)row * 128u + (uint32_t)((c16 ^ (row & 7)) * 16);
}

// ---------------- top-k inserts ----------------
__device__ __forceinline__ void ins_tb3(float s, int gi,
    float& v0, int& i0, float& v1, int& i1, float& v2, int& i2) {
    bool b2 = (s > v2) || (s == v2 && gi < i2);
    if (!b2) return;
    bool b1 = (s > v1) || (s == v1 && gi < i1);
    if (b1) {
        bool b0 = (s > v0) || (s == v0 && gi < i0);
        if (b0) { v2=v1;i2=i1; v1=v0;i1=i0; v0=s;i0=gi; }
        else    { v2=v1;i2=i1; v1=s;i1=gi; }
    } else      { v2=s; i2=gi; }
}

__device__ __forceinline__ void ins_tb4(float s, int gi,
    float& v0, int& i0, float& v1, int& i1, float& v2, int& i2, float& v3, int& i3) {
    if (!(s > v3)) return;
    if (s > v1) {
        if (s > v0) { v3=v2;i3=i2; v2=v1;i2=i1; v1=v0;i1=i0; v0=s;i0=gi; }
        else        { v3=v2;i3=i2; v2=v1;i2=i1; v1=s;i1=gi; }
    } else {
        if (s > v2) { v3=v2;i3=i2; v2=s;i2=gi; }
        else        { v3=s; i3=gi; }
    }
}

// ---------------- fused prep kernel (normalize q + m, emit fp8) ----------------
__global__ void prep_kernel(const float* __restrict__ q, const float* __restrict__ m) {
    int w    = (blockIdx.x * blockDim.x + threadIdx.x) >> 5;
    int lane = threadIdx.x & 31;
    if (w < NQ) {
        float4 v = *(const float4*)(q + (size_t)w * D + lane * 4);
        float ss = v.x*v.x + v.y*v.y + v.z*v.z + v.w*v.w;
        #pragma unroll
        for (int o = 16; o; o >>= 1) ss += __shfl_xor_sync(0xffffffffu, ss, o);
        float inv = 1.0f / fmaxf(sqrtf(ss), 1e-12f);
        float4 r = { v.x*inv, v.y*inv, v.z*inv, v.w*inv };
        *(float4*)(g_qn + (size_t)w * D + lane * 4) = r;
        uint32_t lo = __nv_cvt_float2_to_fp8x2(make_float2(r.x, r.y), __NV_SATFINITE, __NV_E4M3);
        uint32_t hi = __nv_cvt_float2_to_fp8x2(make_float2(r.z, r.w), __NV_SATFINITE, __NV_E4M3);
        g_qf8[(size_t)w * 32 + lane] = (lo & 0xffffu) | (hi << 16);
    } else if (w < NQ + NM) {
        int row = w - NQ;
        float4 v = *(const float4*)(m + (size_t)row * D + lane * 4);
        float ss = v.x*v.x + v.y*v.y + v.z*v.z + v.w*v.w;
        #pragma unroll
        for (int o = 16; o; o >>= 1) ss += __shfl_xor_sync(0xffffffffu, ss, o);
        float inv = 1.0f / fmaxf(sqrtf(ss), 1e-12f);
        if (lane == 0) g_invm[row] = inv;
        float2 a = make_float2(v.x*inv, v.y*inv);
        float2 b = make_float2(v.z*inv, v.w*inv);
        uint32_t lo = __nv_cvt_float2_to_fp8x2(a, __NV_SATFINITE, __NV_E4M3);
        uint32_t hi = __nv_cvt_float2_to_fp8x2(b, __NV_SATFINITE, __NV_E4M3);
        g_mf8[(size_t)row * 32 + lane] = (lo & 0xffffu) | (hi << 16);
    }
}

// ---------------- main FP8 MMA + top-8 kernel ----------------
// 512 threads = 16 warps laid out 4(M) x 4(N). Block tile 128x128, K=128.
// A fragments hoisted into registers; B triple-buffered with a real
// lookahead-1 cp.async pipeline (wait_group 1 keeps the next load in flight).
__global__ __launch_bounds__(512, 1) void mma_topk_kernel() {
    extern __shared__ __align__(16) uint8_t dyn[];

    int tid  = threadIdx.x;
    int wid  = tid >> 5;
    int lane = tid & 31;
    int wm   = wid & 3;       // warp row: 32 queries
    int wn   = wid >> 2;      // warp col: 32 memory rows (0..3)

    uint32_t raw  = s2u(dyn);
    uint32_t base = (raw + 1023u) & ~1023u;
    uint8_t* dbase = (uint8_t*)dyn + (base - raw);
    uint32_t aSm  = base;
    uint32_t bSm  = base + A_BYTES;   // 3 buffers of B_BYTES

    int qbase  = blockIdx.x * QT;
    int chunk  = blockIdx.y;
    int mstart = chunk * CHUNK;
    int mend   = min(mstart + CHUNK, NM);
    int T      = (mend - mstart + NT - 1) / NT;

    const char* mf8 = (const char*)g_mf8;
    const char* qf8 = (const char*)g_qf8;

    // loader geometry: 128 rows, 4 threads/row, 32B each
    int ldRow  = tid >> 2;
    int ldC16  = (tid & 3) * 2;

    // ---- prologue: A tile + B tile 0 (group 0), B tile 1 (group 1) ----
    #pragma unroll
    for (int j = 0; j < 2; ++j)
        cp16(aSm + sw_off(ldRow, ldC16 + j), qf8 + (size_t)(qbase + ldRow) * 128 + (ldC16 + j) * 16);
    {
        int gr = min(mstart + ldRow, NM - 1);
        #pragma unroll
        for (int j = 0; j < 2; ++j)
            cp16(bSm + sw_off(ldRow, ldC16 + j), mf8 + (size_t)gr * 128 + (ldC16 + j) * 16);
    }
    CP_COMMIT();
    if (T > 1) {
        int gr = min(mstart + NT + ldRow, NM - 1);
        #pragma unroll
        for (int j = 0; j < 2; ++j)
            cp16(bSm + B_BYTES + sw_off(ldRow, ldC16 + j), mf8 + (size_t)gr * 128 + (ldC16 + j) * 16);
        CP_COMMIT();
        CP_WAIT1();     // group 0 (A + B0) done, B1 in flight
    } else {
        CP_WAIT0();
    }
    __syncthreads();

    // ---- hoist A fragments (constant across all tiles) ----
    int rowA0 = wm * 32 + (lane & 15);
    int hiA   = lane >> 4;
    uint32_t afr[4][2][4];
    #pragma unroll
    for (int kk = 0; kk < 4; ++kk)
        #pragma unroll
        for (int mt = 0; mt < 2; ++mt)
            ldsm_x4(aSm + sw_off(rowA0 + mt * 16, 2 * kk + hiA),
                    afr[kk][mt][0], afr[kk][mt][1], afr[kk][mt][2], afr[kk][mt][3]);

    // per-thread top-4 for 4 row-slots (rs = mt*2 + h)
    float tv0[4], tv1[4], tv2[4], tv3[4];
    int   ti0[4], ti1[4], ti2[4], ti3[4];
    #pragma unroll
    for (int r = 0; r < 4; ++r) {
        tv0[r]=tv1[r]=tv2[r]=tv3[r] = -2.0f;
        ti0[r]=ti1[r]=ti2[r]=ti3[r] = 0x7fffffff;
    }

    int grp   = lane >> 3;
    int rowB0 = wn * 32 + (lane & 7) + (grp >> 1) * 8;
    int hiB   = grp & 1;

    int bufIdx[3] = {0, 1, 2};   // buffer index for tiles t, t+1, t+2 (mod rotation)

    for (int t = 0; t < T; ++t) {
        int cur = t % NBUF;
        // issue load for t+1 into buf (t+1)%NBUF  -- wait, lookahead 1:
        // note: prologue already loaded t=0 and t=1; so issue t+2's? No:
        // we issued B0 (t=0) and B1 (t=1). In iter t we issue t+2... but that
        // needs 4 buffers with single barrier. Instead: only issue in iter t>=1
        // for tile t+1 (so at most one in flight beyond current).
        if (t >= 1 && t + 1 < T) {
            uint32_t bNext = bSm + ((t + 1) % NBUF) * B_BYTES;
            int gr = min(mstart + (t + 1) * NT + ldRow, NM - 1);
            #pragma unroll
            for (int j = 0; j < 2; ++j)
                cp16(bNext + sw_off(ldRow, ldC16 + j), mf8 + (size_t)gr * 128 + (ldC16 + j) * 16);
            CP_COMMIT();
        }
        // ensure tile t's buffer is ready; allow one group (t+1) in flight
        if (t + 1 < T) CP_WAIT1(); else CP_WAIT0();
        __syncthreads();

        uint32_t bB = bSm + cur * B_BYTES;
        int tb = mstart + t * NT;

        // ---- 128x128x128 block tile, fp8 (4 K-steps of 32) ----
        float acc[2][4][4];
        #pragma unroll
        for (int mt = 0; mt < 2; ++mt)
            #pragma unroll
            for (int nt = 0; nt < 4; ++nt)
                #pragma unroll
                for (int e = 0; e < 4; ++e) acc[mt][nt][e] = 0.0f;

        #pragma unroll
        for (int kk = 0; kk < 4; ++kk) {
            uint32_t b[4][2];
            #pragma unroll
            for (int j = 0; j < 2; ++j)
                ldsm_x4(bB + sw_off(rowB0 + j * 16, 2 * kk + hiB),
                        b[2*j][0], b[2*j][1], b[2*j+1][0], b[2*j+1][1]);
            #pragma unroll
            for (int mt = 0; mt < 2; ++mt)
                #pragma unroll
                for (int nt = 0; nt < 4; ++nt)
                    mma16832(acc[mt][nt], afr[kk][mt], b[nt]);
        }

        // ---- streaming top-4 epilogue ----
        #pragma unroll
        for (int mt = 0; mt < 2; ++mt)
            #pragma unroll
            for (int h = 0; h < 2; ++h) {
                const int rs = mt * 2 + h;
                #pragma unroll
                for (int nt = 0; nt < 4; ++nt)
                    #pragma unroll
                    for (int c = 0; c < 2; ++c) {
                        float s = acc[mt][nt][h * 2 + c];
                        int gi = tb + wn * 32 + nt * 8 + (lane & 3) * 2 + c;
                        if (gi < mend && s > tv3[rs])
                            ins_tb4(s, gi, tv0[rs],ti0[rs], tv1[rs],ti1[rs],
                                           tv2[rs],ti2[rs], tv3[rs],ti3[rs]);
                    }
            }
    }
    (void)bufIdx;

    // ---- merge across the 4 lanes sharing each row (xor 1, 2) ----
    #pragma unroll
    for (int off = 1; off <= 2; off <<= 1) {
        #pragma unroll
        for (int rs = 0; rs < 4; ++rs) {
            float ov0 = __shfl_xor_sync(0xffffffffu, tv0[rs], off);
            int   oi0 = __shfl_xor_sync(0xffffffffu, ti0[rs], off);
            float ov1 = __shfl_xor_sync(0xffffffffu, tv1[rs], off);
            int   oi1 = __shfl_xor_sync(0xffffffffu, ti1[rs], off);
            float ov2 = __shfl_xor_sync(0xffffffffu, tv2[rs], off);
            int   oi2 = __shfl_xor_sync(0xffffffffu, ti2[rs], off);
            float ov3 = __shfl_xor_sync(0xffffffffu, tv3[rs], off);
            int   oi3 = __shfl_xor_sync(0xffffffffu, ti3[rs], off);
            ins_tb4(ov0, oi0, tv0[rs],ti0[rs], tv1[rs],ti1[rs], tv2[rs],ti2[rs], tv3[rs],ti3[rs]);
            ins_tb4(ov1, oi1, tv0[rs],ti0[rs], tv1[rs],ti1[rs], tv2[rs],ti2[rs], tv3[rs],ti3[rs]);
            ins_tb4(ov2, oi2, tv0[rs],ti0[rs], tv1[rs],ti1[rs], tv2[rs],ti2[rs], tv3[rs],ti3[rs]);
            ins_tb4(ov3, oi3, tv0[rs],ti0[rs], tv1[rs],ti1[rs], tv2[rs],ti2[rs], tv3[rs],ti3[rs]);
        }
    }
    __syncthreads();   // all loads drained; smem reusable

    // ---- cross-warp_n merge via smem: [4 wn][128 rows][4 slots] ----
    float* smv = (float*)dbase;                         // 8 KB
    int*   smi = (int*)(dbase + 4 * 128 * 4 * 4);       // 8 KB
    if ((lane & 3) == 0) {
        #pragma unroll
        for (int rs = 0; rs < 4; ++rs) {
            int row = wm * 32 + (rs >> 1) * 16 + (lane >> 2) + (rs & 1) * 8;
            int o = (wn * 128 + row) * 4;
            smv[o+0]=tv0[rs]; smi[o+0]=ti0[rs];
            smv[o+1]=tv1[rs]; smi[o+1]=ti1[rs];
            smv[o+2]=tv2[rs]; smi[o+2]=ti2[rs];
            smv[o+3]=tv3[rs]; smi[o+3]=ti3[rs];
        }
    }
    __syncthreads();
    if (tid < 128) {
        int row = tid;
        float av[16]; int ai[16];
        #pragma unroll
        for (int seg = 0; seg < 4; ++seg)
            #pragma unroll
            for (int j = 0; j < 4; ++j) {
                av[seg*4+j] = smv[(seg * 128 + row) * 4 + j];
                ai[seg*4+j] = smi[(seg * 128 + row) * 4 + j];
            }
        size_t cb = ((size_t)(qbase + row) * NCH + chunk) * KC;
        #pragma unroll
        for (int s = 0; s < KC; ++s) {
            int best = s;
            for (int j = s + 1; j < 16; ++j)
                if (av[j] > av[best]) best = j;
            float bv = av[best]; int bi = ai[best];
            av[best] = av[s]; ai[best] = ai[s];
            av[s] = bv; ai[s] = bi;
            g_cv[cb + s] = bv; g_ci[cb + s] = bi;
        }
    }
}

// ---------------- exact fp32 rescore + final top-3 ----------------
__global__ void rescore_kernel(const float* __restrict__ mem, float* __restrict__ out) {
    __shared__ float sv[8][3];
    __shared__ int   si[8][3];

    int tid   = threadIdx.x;
    int wid   = tid >> 5;
    int lane  = tid & 31;
    int qidx  = blockIdx.x;

    float4 qv = *(const float4*)(g_qn + (size_t)qidx * D + lane * 4);

    float v0 = -2.f, v1 = -2.f, v2 = -2.f;
    int   i0 = 0x7fffffff, i1 = 0x7fffffff, i2 = 0x7fffffff;

    size_t cb = (size_t)qidx * NCH * KC;
    #pragma unroll 1
    for (int j = wid; j < NCH * KC; j += 8) {
        int gi = g_ci[cb + j];
        if ((unsigned)gi >= (unsigned)NM) continue;
        float4 mv = *(const float4*)(mem + (size_t)gi * D + lane * 4);
        float s = qv.x*mv.x + qv.y*mv.y + qv.z*mv.z + qv.w*mv.w;
        #pragma unroll
        for (int o = 16; o; o >>= 1) s += __shfl_xor_sync(0xffffffffu, s, o);
        s *= g_invm[gi];
        ins_tb3(s, gi, v0, i0, v1, i1, v2, i2);
    }
    if (lane == 0) {
        sv[wid][0]=v0; si[wid][0]=i0;
        sv[wid][1]=v1; si[wid][1]=i1;
        sv[wid][2]=v2; si[wid][2]=i2;
    }
    __syncthreads();

    if (tid == 0) {
        float w0 = -2.f, w1 = -2.f, w2 = -2.f;
        int   a0 = 0x7fffffff, a1 = 0x7fffffff, a2 = 0x7fffffff;
        #pragma unroll
        for (int p = 0; p < 8; ++p)
            #pragma unroll
            for (int j = 0; j < 3; ++j)
                ins_tb3(sv[p][j], si[p][j], w0,a0, w1,a1, w2,a2);
        out[(size_t)qidx * 3 + 0] = 1.0f - w0;
        out[(size_t)qidx * 3 + 1] = 1.0f - w1;
        out[(size_t)qidx * 3 + 2] = 1.0f - w2;
        out[(size_t)NQ * 3 + (size_t)qidx * 3 + 0] = (float)a0;
        out[(size_t)NQ * 3 + (size_t)qidx * 3 + 1] = (float)a1;
        out[(size_t)NQ * 3 + (size_t)qidx * 3 + 2] = (float)a2;
    }
}

// ---------------- launch ----------------
extern "C" void kernel_launch(void* const* d_in, const int* in_sizes, int n_in,
                              void* d_out, int out_size) {
    const float* q   = (const float*)d_in[0];
    const float* mem = (const float*)d_in[1];
    float* out = (float*)d_out;

    cudaFuncSetAttribute(mma_topk_kernel,
                         cudaFuncAttributeMaxDynamicSharedMemorySize, SMEM_DYN);

    int prep_warps = NQ + NM;
    prep_kernel<<<(prep_warps * 32 + 255) / 256, 256>>>(q, mem);

    dim3 grid(NQ / QT, NCH);
    mma_topk_kernel<<<grid, 512, SMEM_DYN>>>();

    rescore_kernel<<<NQ, 256>>>(mem, out);
}